// round 1
// baseline (speedup 1.0000x reference)
#include <cuda_runtime.h>
#include <math_constants.h>

#define M_ROWS 32768   // B*L = 8*4096
#define DIMS   256
#define NCODES 1024

// ---------------- scratch (device globals: no allocation allowed) ----------
__device__ float g_z[M_ROWS * DIMS];     // 33.5 MB
__device__ float g_cnorm[NCODES];
__device__ float g_rownorm[M_ROWS];
__device__ int   g_idx[M_ROWS];
__device__ float g_rowloss[M_ROWS];

// ---------------- K1: z = x @ W^T + b  (M=32768, N=256, K=256) -------------
// 128x128x8 tile, 256 threads, 8x8 per-thread microtile.
__global__ __launch_bounds__(256, 2)
void gemm_z_kernel(const float* __restrict__ x,
                   const float* __restrict__ W,
                   const float* __restrict__ b)
{
    __shared__ float sA[8][128];   // A^T tile (k-major)
    __shared__ float sB[8][128];   // B tile: B[k][n] = W[n][k]

    const int tid = threadIdx.x;
    const int rb  = blockIdx.x * 128;       // row base
    const int cb  = blockIdx.y * 128;       // col base (output feature)
    const int tx  = tid & 15;
    const int ty  = tid >> 4;
    const int lr  = tid >> 1;               // 0..127 loader row
    const int lk  = (tid & 1) * 4;          // 0 or 4 loader k offset

    float acc[8][8];
#pragma unroll
    for (int i = 0; i < 8; i++)
#pragma unroll
        for (int j = 0; j < 8; j++) acc[i][j] = 0.f;

    for (int kb = 0; kb < DIMS; kb += 8) {
        float4 av = *reinterpret_cast<const float4*>(&x[(size_t)(rb + lr) * DIMS + kb + lk]);
        float4 bv = *reinterpret_cast<const float4*>(&W[(size_t)(cb + lr) * DIMS + kb + lk]);
        sA[lk + 0][lr] = av.x; sA[lk + 1][lr] = av.y;
        sA[lk + 2][lr] = av.z; sA[lk + 3][lr] = av.w;
        sB[lk + 0][lr] = bv.x; sB[lk + 1][lr] = bv.y;
        sB[lk + 2][lr] = bv.z; sB[lk + 3][lr] = bv.w;
        __syncthreads();
#pragma unroll
        for (int kk = 0; kk < 8; kk++) {
            float4 a0 = *reinterpret_cast<float4*>(&sA[kk][ty * 8]);
            float4 a1 = *reinterpret_cast<float4*>(&sA[kk][ty * 8 + 4]);
            float4 b0 = *reinterpret_cast<float4*>(&sB[kk][tx * 8]);
            float4 b1 = *reinterpret_cast<float4*>(&sB[kk][tx * 8 + 4]);
            float a[8] = {a0.x, a0.y, a0.z, a0.w, a1.x, a1.y, a1.z, a1.w};
            float bbv[8] = {b0.x, b0.y, b0.z, b0.w, b1.x, b1.y, b1.z, b1.w};
#pragma unroll
            for (int i = 0; i < 8; i++)
#pragma unroll
                for (int j = 0; j < 8; j++)
                    acc[i][j] += a[i] * bbv[j];
        }
        __syncthreads();
    }

#pragma unroll
    for (int i = 0; i < 8; i++) {
        int r = rb + ty * 8 + i;
#pragma unroll
        for (int j = 0; j < 8; j += 4) {
            int c = cb + tx * 8 + j;
            float4 v;
            v.x = acc[i][j + 0] + b[c + 0];
            v.y = acc[i][j + 1] + b[c + 1];
            v.z = acc[i][j + 2] + b[c + 2];
            v.w = acc[i][j + 3] + b[c + 3];
            *reinterpret_cast<float4*>(&g_z[(size_t)r * DIMS + c]) = v;
        }
    }
}

// ---------------- K2a: row norms of z (one warp per row) -------------------
__global__ void rownorm_kernel()
{
    int warp = (blockIdx.x * blockDim.x + threadIdx.x) >> 5;
    int lane = threadIdx.x & 31;
    if (warp >= M_ROWS) return;
    const float* p = &g_z[(size_t)warp * DIMS];
    float s = 0.f;
#pragma unroll
    for (int i = 0; i < DIMS / 32; i++) {
        float v = p[lane + 32 * i];
        s += v * v;
    }
#pragma unroll
    for (int o = 16; o > 0; o >>= 1) s += __shfl_down_sync(0xffffffffu, s, o);
    if (lane == 0) g_rownorm[warp] = s;
}

// ---------------- K2b: code norms ------------------------------------------
__global__ void cnorm_kernel(const float* __restrict__ emb)
{
    int warp = (blockIdx.x * blockDim.x + threadIdx.x) >> 5;
    int lane = threadIdx.x & 31;
    if (warp >= NCODES) return;
    const float* p = &emb[(size_t)warp * DIMS];
    float s = 0.f;
#pragma unroll
    for (int i = 0; i < DIMS / 32; i++) {
        float v = p[lane + 32 * i];
        s += v * v;
    }
#pragma unroll
    for (int o = 16; o > 0; o >>= 1) s += __shfl_down_sync(0xffffffffu, s, o);
    if (lane == 0) g_cnorm[warp] = s;
}

// ---------------- K3: score GEMM + argmin (dominant kernel) ----------------
// dist[m][n] = fl( fl(rownorm[m] + cnorm[n]) - fl(2 * (z_m . e_n)) )
// matching the reference's fp32 rounding structure; first-index tie-break.
__global__ __launch_bounds__(256, 2)
void argmin_kernel(const float* __restrict__ emb)
{
    __shared__ float sZ[8][128];
    __shared__ float sE[8][128];
    __shared__ float sval[128][16];
    __shared__ int   sidxm[128][16];

    const int tid = threadIdx.x;
    const int rb  = blockIdx.x * 128;
    const int tx  = tid & 15;
    const int ty  = tid >> 4;
    const int lr  = tid >> 1;
    const int lk  = (tid & 1) * 4;

    float minv[8];
    int   mini[8];
    float rn[8];
#pragma unroll
    for (int i = 0; i < 8; i++) {
        minv[i] = CUDART_INF_F;
        mini[i] = 0;
        rn[i]   = g_rownorm[rb + ty * 8 + i];
    }

    for (int nc = 0; nc < NCODES; nc += 128) {
        float acc[8][8];
#pragma unroll
        for (int i = 0; i < 8; i++)
#pragma unroll
            for (int j = 0; j < 8; j++) acc[i][j] = 0.f;

        for (int kb = 0; kb < DIMS; kb += 8) {
            float4 zv = *reinterpret_cast<const float4*>(&g_z[(size_t)(rb + lr) * DIMS + kb + lk]);
            float4 ev = *reinterpret_cast<const float4*>(&emb[(size_t)(nc + lr) * DIMS + kb + lk]);
            sZ[lk + 0][lr] = zv.x; sZ[lk + 1][lr] = zv.y;
            sZ[lk + 2][lr] = zv.z; sZ[lk + 3][lr] = zv.w;
            sE[lk + 0][lr] = ev.x; sE[lk + 1][lr] = ev.y;
            sE[lk + 2][lr] = ev.z; sE[lk + 3][lr] = ev.w;
            __syncthreads();
#pragma unroll
            for (int kk = 0; kk < 8; kk++) {
                float4 a0 = *reinterpret_cast<float4*>(&sZ[kk][ty * 8]);
                float4 a1 = *reinterpret_cast<float4*>(&sZ[kk][ty * 8 + 4]);
                float4 b0 = *reinterpret_cast<float4*>(&sE[kk][tx * 8]);
                float4 b1 = *reinterpret_cast<float4*>(&sE[kk][tx * 8 + 4]);
                float a[8] = {a0.x, a0.y, a0.z, a0.w, a1.x, a1.y, a1.z, a1.w};
                float e[8] = {b0.x, b0.y, b0.z, b0.w, b1.x, b1.y, b1.z, b1.w};
#pragma unroll
                for (int i = 0; i < 8; i++)
#pragma unroll
                    for (int j = 0; j < 8; j++)
                        acc[i][j] += a[i] * e[j];
            }
            __syncthreads();
        }

#pragma unroll
        for (int j = 0; j < 8; j++) {
            int col = nc + tx * 8 + j;
            float cn = g_cnorm[col];
#pragma unroll
            for (int i = 0; i < 8; i++) {
                float t    = __fadd_rn(rn[i], cn);
                float dist = __fadd_rn(t, -__fmul_rn(2.0f, acc[i][j]));
                // cols visited in ascending order within a thread -> strict <
                // keeps the first (lowest-index) minimum.
                if (dist < minv[i]) { minv[i] = dist; mini[i] = col; }
            }
        }
    }

#pragma unroll
    for (int i = 0; i < 8; i++) {
        sval[ty * 8 + i][tx]  = minv[i];
        sidxm[ty * 8 + i][tx] = mini[i];
    }
    __syncthreads();
    if (tid < 128) {
        float bv = sval[tid][0];
        int   bi = sidxm[tid][0];
#pragma unroll
        for (int t = 1; t < 16; t++) {
            float v  = sval[tid][t];
            int   ii = sidxm[tid][t];
            if (v < bv || (v == bv && ii < bi)) { bv = v; bi = ii; }
        }
        g_idx[rb + tid] = bi;
    }
}

// ---------------- K4: gather quant, write indices, per-row loss ------------
__global__ void gather_kernel(const float* __restrict__ emb,
                              float* __restrict__ outq,
                              float* __restrict__ outi)
{
    __shared__ float ws[8];
    int row = blockIdx.x;
    int d   = threadIdx.x;
    int idx = g_idx[row];
    float e = emb[(size_t)idx * DIMS + d];
    float z = g_z[(size_t)row * DIMS + d];
    outq[(size_t)row * DIMS + d] = e;
    float diff = e - z;
    float s = diff * diff;
#pragma unroll
    for (int o = 16; o > 0; o >>= 1) s += __shfl_down_sync(0xffffffffu, s, o);
    int lane = d & 31, w = d >> 5;
    if (lane == 0) ws[w] = s;
    __syncthreads();
    if (d == 0) {
        float tot = 0.f;
#pragma unroll
        for (int i = 0; i < 8; i++) tot += ws[i];
        g_rowloss[row] = tot;
        outi[row] = (float)idx;
    }
}

// ---------------- K5: deterministic loss reduction -------------------------
__global__ void loss_kernel(float* __restrict__ outl)
{
    __shared__ double sd[256];
    double s = 0.0;
    for (int i = threadIdx.x; i < M_ROWS; i += 256) s += (double)g_rowloss[i];
    sd[threadIdx.x] = s;
    __syncthreads();
    for (int o = 128; o > 0; o >>= 1) {
        if (threadIdx.x < o) sd[threadIdx.x] += sd[threadIdx.x + o];
        __syncthreads();
    }
    if (threadIdx.x == 0) {
        // loss = BETA*mean + mean = 1.25 * mean((quant - z)^2)
        outl[0] = (float)(1.25 * sd[0] / 8388608.0);
    }
}

// ---------------- launch ----------------------------------------------------
extern "C" void kernel_launch(void* const* d_in, const int* in_sizes, int n_in,
                              void* d_out, int out_size)
{
    const float* x   = (const float*)d_in[0];   // [8,4096,256]
    const float* W   = (const float*)d_in[1];   // [256,256]
    const float* b   = (const float*)d_in[2];   // [256]
    const float* emb = (const float*)d_in[3];   // [1024,256]

    float* out  = (float*)d_out;
    float* outq = out;                          // quant: 8*4096*256
    float* outi = out + (size_t)M_ROWS * DIMS;  // indices: 32768 (as float)
    float* outl = outi + M_ROWS;                // loss: 1

    dim3 g1(M_ROWS / 128, DIMS / 128);
    gemm_z_kernel<<<g1, 256>>>(x, W, b);
    rownorm_kernel<<<M_ROWS / 8, 256>>>();
    cnorm_kernel<<<NCODES / 8, 256>>>(emb);
    argmin_kernel<<<M_ROWS / 128, 256>>>(emb);
    gather_kernel<<<M_ROWS, 256>>>(emb, outq, outi);
    loss_kernel<<<1, 256>>>(outl);
}